// round 16
// baseline (speedup 1.0000x reference)
#include <cuda_runtime.h>
#include <cuda_bf16.h>
#include <cstdint>

// LearnedTaskSpecificLinear via HMMA bf16 split precision, cp.async-staged.
// out[n,o] = sum_i x[n,i] * W[task_ids[n], i, o],  N=2048, I=O=512, T=64.
//
// Block = (task, 256-col tile), 512 threads (16 warps = 2m x 8n).
// Grid 64x2 = 128 blocks -> single wave on 148 SMs.
// W is staged gmem->smem fp32 by a 2-deep cp.async pipeline (issued 2 stages
// ahead); convert reads staging via LDS, so DRAM latency is off the critical
// path. A (x) is register-prefetched before the cp-wait each stage.
// Split: v = hi(bf16) + lo(bf16 residual); acc += Ah*Bh + Ah*Bl + Al*Bh (fp32).
// Dead m16 tiles (row padding beyond n) are fully predicated off.

#define NUM_TASKS 64
#define N_ROWS    2048
#define IN_SIZE   512
#define OUT_SIZE  512

#define NT        512
#define PER_THREAD (N_ROWS / NT)     // 4
#define M_TILE    64
#define N_TILE    256
#define K_TILE    64
#define N_STAGES  (IN_SIZE / K_TILE) // 8

// dynamic smem layout
#define OFF_A_HI  0                      //  64 rows x 128B
#define OFF_A_LO  8192
#define OFF_B_HI  16384                  // 256 rows x 128B
#define OFF_B_LO  49152
#define OFF_WST   81920                  // staging: 2 x (64k x 1024B) fp32
#define WST_BYTES 65536
#define DYN_SMEM  (OFF_WST + 2 * WST_BYTES)   // 212992 (208KB)

typedef unsigned long long ull;

static __device__ __forceinline__ uint32_t swz(uint32_t o) {
    return o ^ ((o >> 3) & 0x70);
}
static __device__ __forceinline__ uint32_t smem_u32(const void* p) {
    uint32_t a;
    asm("{ .reg .u64 t; cvta.to.shared.u64 t, %1; cvt.u32.u64 %0, t; }"
        : "=r"(a) : "l"(p));
    return a;
}
// pack: e0 -> low half, e1 -> high half
static __device__ __forceinline__ uint32_t bfhi(float e0, float e1) {
    uint32_t r;
    asm("cvt.rn.bf16x2.f32 %0, %1, %2;" : "=r"(r) : "f"(e1), "f"(e0));
    return r;
}
static __device__ __forceinline__ uint32_t bflo(float e0, float e1, uint32_t h) {
    float h0 = __uint_as_float(h << 16);
    float h1 = __uint_as_float(h & 0xffff0000u);
    return bfhi(e0 - h0, e1 - h1);
}
static __device__ __forceinline__ void ldsm_x4(uint32_t& r0, uint32_t& r1,
                                               uint32_t& r2, uint32_t& r3,
                                               uint32_t addr) {
    asm volatile("ldmatrix.sync.aligned.m8n8.x4.shared.b16 {%0,%1,%2,%3}, [%4];"
                 : "=r"(r0), "=r"(r1), "=r"(r2), "=r"(r3) : "r"(addr));
}
static __device__ __forceinline__ void mma_bf16(float* d, const uint32_t* a,
                                                uint32_t b0, uint32_t b1) {
    asm volatile(
        "mma.sync.aligned.m16n8k16.row.col.f32.bf16.bf16.f32 "
        "{%0,%1,%2,%3}, {%4,%5,%6,%7}, {%8,%9}, {%0,%1,%2,%3};"
        : "+f"(d[0]), "+f"(d[1]), "+f"(d[2]), "+f"(d[3])
        : "r"(a[0]), "r"(a[1]), "r"(a[2]), "r"(a[3]), "r"(b0), "r"(b1));
}
static __device__ __forceinline__ void cp16(uint32_t dst_smem, const void* src) {
    asm volatile("cp.async.cg.shared.global [%0], [%1], 16;\n"
                 :: "r"(dst_smem), "l"(src));
}
static __device__ __forceinline__ void cp_commit() {
    asm volatile("cp.async.commit_group;\n");
}
static __device__ __forceinline__ void cp_wait1() {
    asm volatile("cp.async.wait_group 1;\n");
}

__global__ __launch_bounds__(NT, 1)
void task_linear_cp_kernel(const float* __restrict__ x,
                           const int* __restrict__ tid32,
                           const float* __restrict__ W,
                           float* __restrict__ out) {
    extern __shared__ __align__(128) char dsm[];
    const int t    = blockIdx.x;
    const int ct   = blockIdx.y;
    const int tid  = threadIdx.x;
    const int lane = tid & 31;
    const int wid  = tid >> 5;      // 0..15
    const int mw   = wid >> 3;      // m-half (0/1): rows mw*32..+32
    const int nw   = wid & 7;       // n-eighth: cols nw*32..+32

    __shared__ unsigned short rows[N_ROWS];
    __shared__ int warp_sums[NT / 32];
    __shared__ int s_n, s_is64;

    const uint32_t sb = smem_u32(dsm);

    if (tid == 0) s_is64 = 0;
    __syncthreads();

    // dtype detect (int32 vs int64): odd-index words of int64 data are zero.
    // Every thread probes one of the first 256 entries so ALL warps see data.
    {
        int v = tid32[2 * (tid & 255) + 1];
        #pragma unroll
        for (int o = 16; o > 0; o >>= 1) v |= __shfl_xor_sync(0xffffffffu, v, o);
        if (lane == 0 && v == 0) s_is64 = 1;
    }
    __syncthreads();
    const int stride = s_is64 ? 2 : 1;

    // Deterministic row list (index order) via prefix scan.
    {
        const int base = tid * PER_THREAD;
        int match = 0;
        #pragma unroll
        for (int j = 0; j < PER_THREAD; j++)
            if (tid32[(base + j) * stride] == t) match |= (1 << j);
        int c = __popc(match);
        int incl = c;
        #pragma unroll
        for (int o = 1; o < 32; o <<= 1) {
            int v = __shfl_up_sync(0xffffffffu, incl, o);
            if (lane >= o) incl += v;
        }
        if (lane == 31) warp_sums[wid] = incl;
        __syncthreads();
        int woff = 0;
        #pragma unroll
        for (int q = 0; q < NT / 32; q++)
            if (q < wid) woff += warp_sums[q];
        int pos = woff + incl - c;
        #pragma unroll
        for (int j = 0; j < PER_THREAD; j++)
            if (match & (1 << j)) rows[pos++] = (unsigned short)(base + j);
        if (tid == NT - 1) s_n = pos;
    }
    __syncthreads();
    const int n = s_n;
    const int n16 = (n + 15) & ~15;

    // Conversion thread mappings:
    //   A: row ar = tid&63, k-eighth aq = tid>>6 (8 floats = 2 float4)
    //   B: col bn = tid&255, k-half bq = tid>>8 (32 k each)
    const int ar = tid & 63;
    const int aq = tid >> 6;
    const int bn = tid & 255;
    const int bq = tid >> 8;

    const float* Wbase = W + (size_t)t * IN_SIZE * OUT_SIZE + (size_t)ct * N_TILE;
    const uint32_t wst0 = sb + OFF_WST;

    for (int m0 = 0; m0 < n; m0 += M_TILE) {
        float acc[2][4][4];
        #pragma unroll
        for (int tm = 0; tm < 2; tm++)
            #pragma unroll
            for (int tn = 0; tn < 4; tn++)
                #pragma unroll
                for (int c = 0; c < 4; c++) acc[tm][tn][c] = 0.f;

        const bool aactive = (m0 + ar) < n16;
        const bool avalid  = (m0 + ar) < n;
        const float* xrow = x + (size_t)(avalid ? rows[m0 + ar] : 0) * IN_SIZE;

        bool tmlive[2];
        #pragma unroll
        for (int tm = 0; tm < 2; tm++)
            tmlive[tm] = (m0 + mw * 32 + tm * 16) < n;
        const bool any_tm = tmlive[0] | tmlive[1];

        // cp.async issue for W stage slice [K_TILE][N_TILE] fp32 (64KB)
        auto cp_w = [&](int st, int buf) {
            const int kbase = st * K_TILE;
            #pragma unroll
            for (int q = 0; q < 8; q++) {
                int j   = tid + q * NT;      // 0..4095
                int kk  = j >> 6;            // 0..63
                int c16 = j & 63;            // 16B chunk in 1024B row
                cp16(wst0 + (uint32_t)buf * WST_BYTES + (uint32_t)(kk * 1024 + c16 * 16),
                     Wbase + (size_t)(kbase + kk) * OUT_SIZE + c16 * 4);
            }
        };

        // pipeline prologue: stages 0,1 in flight
        cp_w(0, 0); cp_commit();
        cp_w(1, 1); cp_commit();

        for (int st = 0; st < N_STAGES; st++) {
            const int buf = st & 1;
            const int kbase = st * K_TILE;

            // A prefetch (register) — overlaps the cp.async wait below
            float4 av[2];
            if (aactive) {
                const float* xp = xrow + kbase + aq * 8;
                av[0] = avalid ? *(const float4*)(xp + 0)
                               : make_float4(0.f, 0.f, 0.f, 0.f);
                av[1] = avalid ? *(const float4*)(xp + 4)
                               : make_float4(0.f, 0.f, 0.f, 0.f);
            }

            cp_wait1();           // W stage st landed (<=1 group pending)
            __syncthreads();      // visible to all; prev MMA reads also done

            // ---- convert A: regs -> bf16 hi/lo smem ----
            if (aactive) {
                #pragma unroll
                for (int j = 0; j < 2; j++) {
                    uint32_t h0 = bfhi(av[j].x, av[j].y), h1 = bfhi(av[j].z, av[j].w);
                    uint32_t l0 = bflo(av[j].x, av[j].y, h0), l1 = bflo(av[j].z, av[j].w, h1);
                    uint32_t off = swz((uint32_t)(ar * 128 + (aq * 8 + j * 4) * 2));
                    *(ull*)(dsm + OFF_A_HI + off) = ((ull)h1 << 32) | h0;
                    *(ull*)(dsm + OFF_A_LO + off) = ((ull)l1 << 32) | l0;
                }
            }
            // ---- convert B: staging fp32 [k][n] -> bf16 [n][k] hi/lo ----
            {
                const float* wst = (const float*)(dsm + OFF_WST + buf * WST_BYTES);
                #pragma unroll
                for (int p = 0; p < 16; p++) {
                    float e0 = wst[(bq * 32 + 2 * p) * N_TILE + bn];
                    float e1 = wst[(bq * 32 + 2 * p + 1) * N_TILE + bn];
                    uint32_t h = bfhi(e0, e1);
                    uint32_t l = bflo(e0, e1, h);
                    uint32_t off = swz((uint32_t)(bn * 128 + (bq * 32 + 2 * p) * 2));
                    *(uint32_t*)(dsm + OFF_B_HI + off) = h;
                    *(uint32_t*)(dsm + OFF_B_LO + off) = l;
                }
            }
            __syncthreads();      // bf16 tiles ready; staging[buf] fully read

            // refill freed staging buffer (flies over the MMA phase)
            if (st + 2 < N_STAGES) cp_w(st + 2, buf);
            cp_commit();          // empty commits keep group accounting uniform

            // ---- 4 k16 steps of HMMA (dead m16 tiles skipped) ----
            if (any_tm) {
                #pragma unroll
                for (int ks = 0; ks < 4; ks++) {
                    const uint32_t kcol =
                        (uint32_t)((ks * 16 + ((lane >> 4) & 1) * 8) * 2);

                    uint32_t ah[2][4], al[2][4], bh[2][4], bl[2][4];
                    #pragma unroll
                    for (int tm = 0; tm < 2; tm++) {
                        if (!tmlive[tm]) continue;
                        uint32_t off = swz(
                            (uint32_t)((mw * 32 + tm * 16 + (lane & 15)) * 128) + kcol);
                        ldsm_x4(ah[tm][0], ah[tm][1], ah[tm][2], ah[tm][3],
                                sb + OFF_A_HI + off);
                        ldsm_x4(al[tm][0], al[tm][1], al[tm][2], al[tm][3],
                                sb + OFF_A_LO + off);
                    }
                    #pragma unroll
                    for (int tp = 0; tp < 2; tp++) {
                        uint32_t off = swz(
                            (uint32_t)((nw * 32 + tp * 16 + (lane & 15)) * 128) + kcol);
                        ldsm_x4(bh[tp][0], bh[tp][1], bh[tp][2], bh[tp][3],
                                sb + OFF_B_HI + off);
                        ldsm_x4(bl[tp][0], bl[tp][1], bl[tp][2], bl[tp][3],
                                sb + OFF_B_LO + off);
                    }
                    #pragma unroll
                    for (int tm = 0; tm < 2; tm++) {
                        if (!tmlive[tm]) continue;
                        #pragma unroll
                        for (int tn = 0; tn < 4; tn++) {
                            const int tp = tn >> 1, sl = tn & 1;
                            mma_bf16(acc[tm][tn], ah[tm], bh[tp][sl], bh[tp][2 + sl]);
                            mma_bf16(acc[tm][tn], ah[tm], bl[tp][sl], bl[tp][2 + sl]);
                            mma_bf16(acc[tm][tn], al[tm], bh[tp][sl], bh[tp][2 + sl]);
                        }
                    }
                }
            }
            // NOTE: next iteration's __syncthreads (after cp_wait1) separates
            // these MMA reads from the next convert's tile overwrite.
        }

        // ---- epilogue: D fragments -> out (dead tiles skipped) ----
        #pragma unroll
        for (int tm = 0; tm < 2; tm++) {
            if (!tmlive[tm]) continue;
            #pragma unroll
            for (int tn = 0; tn < 4; tn++) {
                const int col = ct * N_TILE + nw * 32 + tn * 8 + (lane & 3) * 2;
                int m_lo = m0 + mw * 32 + tm * 16 + (lane >> 2);
                if (m_lo < n) {
                    float* o = out + (size_t)rows[m_lo] * OUT_SIZE + col;
                    o[0] = acc[tm][tn][0];
                    o[1] = acc[tm][tn][1];
                }
                int m_hi = m_lo + 8;
                if (m_hi < n) {
                    float* o = out + (size_t)rows[m_hi] * OUT_SIZE + col;
                    o[0] = acc[tm][tn][2];
                    o[1] = acc[tm][tn][3];
                }
            }
        }
        __syncthreads();   // smem reuse safety across m-tiles
    }
}

extern "C" void kernel_launch(void* const* d_in, const int* in_sizes, int n_in,
                              void* d_out, int out_size) {
    const float* x = nullptr;
    const int*   tids = nullptr;
    const float* W = nullptr;
    for (int i = 0; i < n_in; i++) {
        if (in_sizes[i] == N_ROWS * IN_SIZE)                    x = (const float*)d_in[i];
        else if (in_sizes[i] == N_ROWS)                         tids = (const int*)d_in[i];
        else if (in_sizes[i] == NUM_TASKS * IN_SIZE * OUT_SIZE) W = (const float*)d_in[i];
    }
    float* out = (float*)d_out;

    cudaFuncSetAttribute(task_linear_cp_kernel,
                         cudaFuncAttributeMaxDynamicSharedMemorySize, DYN_SMEM);
    dim3 grid(NUM_TASKS, OUT_SIZE / N_TILE);   // 64 x 2 = 128 blocks (1 wave)
    task_linear_cp_kernel<<<grid, NT, DYN_SMEM>>>(x, tids, W, out);
}